// round 1
// baseline (speedup 1.0000x reference)
#include <cuda_runtime.h>

// Problem constants (fixed by the reference setup_inputs)
static constexpr int BATCH = 8;
static constexpr int SEQ   = 16384;
static constexpr int CH    = 256;
static constexpr int TOPN  = 2048;
static constexpr int ROWS  = BATCH * SEQ;      // 131072
static constexpr int K1_BLOCKS = ROWS / 16;    // 8192 blocks, 16 rows each

// Scratch (no allocations allowed -> device globals)
__device__ float g_score[ROWS];
__device__ float g_psum[K1_BLOCKS];
__device__ float g_psq[K1_BLOCKS];
__device__ unsigned g_idx[BATCH * TOPN];

// ---------------------------------------------------------------------------
// K1: score[row] = dot(x_in[row,:], w) + b ; per-block partial sum/sumsq
// One warp per row, float4 loads (coalesced 128B per warp access).
// ---------------------------------------------------------------------------
__global__ __launch_bounds__(512) void score_kernel(const float* __restrict__ x,
                                                    const float* __restrict__ w,
                                                    const float* __restrict__ bias) {
    int warp = threadIdx.x >> 5;
    int lane = threadIdx.x & 31;
    size_t row = (size_t)blockIdx.x * 16 + warp;

    const float4* xr = (const float4*)(x + row * CH);
    const float4* wv = (const float4*)w;
    float4 a0 = xr[lane];      float4 w0 = wv[lane];
    float4 a1 = xr[lane + 32]; float4 w1 = wv[lane + 32];
    float s = a0.x * w0.x + a0.y * w0.y + a0.z * w0.z + a0.w * w0.w
            + a1.x * w1.x + a1.y * w1.y + a1.z * w1.z + a1.w * w1.w;
#pragma unroll
    for (int off = 16; off > 0; off >>= 1)
        s += __shfl_xor_sync(0xffffffffu, s, off);

    __shared__ float ws[16], wq[16];
    if (lane == 0) {
        float sc = s + bias[0];
        g_score[row] = sc;
        ws[warp] = sc;
        wq[warp] = sc * sc;
    }
    __syncthreads();
    if (threadIdx.x == 0) {
        float S = 0.f, Q = 0.f;
#pragma unroll
        for (int i = 0; i < 16; i++) { S += ws[i]; Q += wq[i]; }
        g_psum[blockIdx.x] = S;
        g_psq[blockIdx.x]  = Q;
    }
}

// ---------------------------------------------------------------------------
// K2: one CTA per batch. Finalize mean/var, build stable sort keys
// (bits(relu(normalized)) << 32) | index, radix-select the rank-(TOPN-1)
// key, collect the TOPN smallest keys, bitonic-sort them (stable order ==
// ascending 64-bit key since index is baked into the low bits), emit indices.
// ---------------------------------------------------------------------------
__global__ __launch_bounds__(1024) void select_kernel(const float* __restrict__ gamma,
                                                      const float* __restrict__ beta) {
    extern __shared__ unsigned long long dyn[];
    unsigned long long* keys = dyn;          // SEQ entries
    unsigned long long* sel  = dyn + SEQ;    // TOPN entries

    __shared__ unsigned hist[256];
    __shared__ float red1[1024], red2[1024];
    __shared__ unsigned long long prefix_s;
    __shared__ int k_s;
    __shared__ unsigned cnt_s;

    const int tid = threadIdx.x;
    const int b   = blockIdx.x;

    // --- global mean / var from K1 partials (deterministic tree reduce) ---
    float S = 0.f, Q = 0.f;
    for (int i = tid; i < K1_BLOCKS; i += 1024) { S += g_psum[i]; Q += g_psq[i]; }
    red1[tid] = S; red2[tid] = Q;
    __syncthreads();
    for (int off = 512; off > 0; off >>= 1) {
        if (tid < off) { red1[tid] += red1[tid + off]; red2[tid] += red2[tid + off]; }
        __syncthreads();
    }
    float mean = red1[0] / (float)ROWS;
    float var  = red2[0] / (float)ROWS - mean * mean;
    if (var < 0.f) var = 0.f;
    float scale = rsqrtf(var + 1e-5f) * gamma[0];
    float shift = beta[0] - mean * scale;

    // --- build keys ---
    const float* sc = g_score + (size_t)b * SEQ;
    for (int i = tid; i < SEQ; i += 1024) {
        float r = fmaxf(0.f, fmaf(sc[i], scale, shift));  // relu(normalized), >= +0
        keys[i] = ((unsigned long long)__float_as_uint(r) << 32) | (unsigned)i;
    }
    if (tid == 0) { prefix_s = 0ULL; k_s = TOPN - 1; cnt_s = 0u; }
    __syncthreads();

    // --- radix-select the key of rank TOPN-1 (keys are unique) ---
    unsigned long long prefix = 0ULL;
    for (int d = 7; d >= 0; --d) {
        for (int i = tid; i < 256; i += 1024) hist[i] = 0u;
        __syncthreads();
        const int sh = d * 8;
        const unsigned long long pmask = (d == 7) ? 0ULL : (~0ULL << (sh + 8));
        for (int i = tid; i < SEQ; i += 1024) {
            unsigned long long key = keys[i];
            if ((key & pmask) == prefix)
                atomicAdd(&hist[(unsigned)(key >> sh) & 255u], 1u);
        }
        __syncthreads();
        if (tid == 0) {
            int k = k_s;
            int bin = 0;
            for (;;) {
                int c = (int)hist[bin];
                if (k < c) break;
                k -= c; ++bin;
            }
            prefix_s = prefix | ((unsigned long long)bin << sh);
            k_s = k;
        }
        __syncthreads();
        prefix = prefix_s;
    }
    const unsigned long long cutoff = prefix;  // exactly TOPN keys are <= cutoff

    // --- collect the selected keys (unordered) ---
    for (int i = tid; i < SEQ; i += 1024) {
        unsigned long long key = keys[i];
        if (key <= cutoff) {
            unsigned p = atomicAdd(&cnt_s, 1u);
            sel[p] = key;
        }
    }
    __syncthreads();

    // --- bitonic sort of TOPN keys, ascending ---
    for (int k = 2; k <= TOPN; k <<= 1) {
        for (int j = k >> 1; j > 0; j >>= 1) {
            for (int i = tid; i < TOPN; i += 1024) {
                int l = i ^ j;
                if (l > i) {
                    unsigned long long a = sel[i], c = sel[l];
                    bool asc = ((i & k) == 0);
                    if ((a > c) == asc) { sel[i] = c; sel[l] = a; }
                }
            }
            __syncthreads();
        }
    }

    for (int r = tid; r < TOPN; r += 1024)
        g_idx[b * TOPN + r] = (unsigned)(sel[r] & 0xffffffffu);
}

// ---------------------------------------------------------------------------
// K3: gather rows of x_select: out[b, r, :] = x_select[b, idx[b,r], :]
// 64 threads per row (float4 per thread), 4 rows per 256-thread block.
// ---------------------------------------------------------------------------
__global__ __launch_bounds__(256) void gather_kernel(const float* __restrict__ xs,
                                                     float* __restrict__ out) {
    int rid  = blockIdx.x * 4 + (threadIdx.x >> 6);   // 0 .. BATCH*TOPN-1
    int lane = threadIdx.x & 63;
    int b    = rid >> 11;                              // TOPN == 2048
    unsigned idx = g_idx[rid];
    const float4* src = (const float4*)(xs + ((size_t)b * SEQ + idx) * CH);
    float4* dst = (float4*)(out + (size_t)rid * CH);
    dst[lane] = src[lane];
}

// ---------------------------------------------------------------------------
extern "C" void kernel_launch(void* const* d_in, const int* in_sizes, int n_in,
                              void* d_out, int out_size) {
    const float* x_in  = (const float*)d_in[0];
    const float* x_sel = (const float*)d_in[1];
    const float* w     = (const float*)d_in[2];
    const float* bias  = (const float*)d_in[3];
    const float* gamma = (const float*)d_in[4];
    const float* beta  = (const float*)d_in[5];
    float* out = (float*)d_out;

    const int sel_smem = (SEQ + TOPN) * (int)sizeof(unsigned long long);  // 147456 B
    cudaFuncSetAttribute(select_kernel,
                         cudaFuncAttributeMaxDynamicSharedMemorySize, sel_smem);

    score_kernel<<<K1_BLOCKS, 512>>>(x_in, w, bias);
    select_kernel<<<BATCH, 1024, sel_smem>>>(gamma, beta);
    gather_kernel<<<(BATCH * TOPN) / 4, 256>>>(x_sel, out);
}

// round 2
// speedup vs baseline: 1.2239x; 1.2239x over previous
#include <cuda_runtime.h>

static constexpr int BATCH = 8;
static constexpr int SEQ   = 16384;
static constexpr int CH    = 256;
static constexpr int TOPN  = 2048;
static constexpr int ROWS  = BATCH * SEQ;        // 131072
static constexpr int ROWS_PER_BLOCK = 32;
static constexpr int K1_BLOCKS = ROWS / ROWS_PER_BLOCK;  // 4096

__device__ float g_score[ROWS];
__device__ float g_psum[K1_BLOCKS];
__device__ float g_psq[K1_BLOCKS];
__device__ unsigned g_idx[BATCH * TOPN];

// ---------------------------------------------------------------------------
// K1: score[row] = dot(x_in[row,:], w) + b.  Two rows per warp -> 4
// independent 128B x-loads in flight per thread (MLP=4), streaming loads.
// ---------------------------------------------------------------------------
__global__ __launch_bounds__(512) void score_kernel(const float* __restrict__ x,
                                                    const float* __restrict__ w,
                                                    const float* __restrict__ bias) {
    int warp = threadIdx.x >> 5;
    int lane = threadIdx.x & 31;
    size_t r0 = (size_t)blockIdx.x * ROWS_PER_BLOCK + warp * 2;

    const float4* x0 = (const float4*)(x + r0 * CH);
    const float4* x1 = (const float4*)(x + (r0 + 1) * CH);
    const float4* wv = (const float4*)w;

    float4 a0 = __ldcs(x0 + lane);
    float4 a1 = __ldcs(x0 + lane + 32);
    float4 b0 = __ldcs(x1 + lane);
    float4 b1 = __ldcs(x1 + lane + 32);
    float4 w0 = wv[lane];
    float4 w1 = wv[lane + 32];

    float s0 = a0.x*w0.x + a0.y*w0.y + a0.z*w0.z + a0.w*w0.w
             + a1.x*w1.x + a1.y*w1.y + a1.z*w1.z + a1.w*w1.w;
    float s1 = b0.x*w0.x + b0.y*w0.y + b0.z*w0.z + b0.w*w0.w
             + b1.x*w1.x + b1.y*w1.y + b1.z*w1.z + b1.w*w1.w;
#pragma unroll
    for (int off = 16; off > 0; off >>= 1) {
        s0 += __shfl_xor_sync(0xffffffffu, s0, off);
        s1 += __shfl_xor_sync(0xffffffffu, s1, off);
    }

    __shared__ float ws[ROWS_PER_BLOCK], wq[ROWS_PER_BLOCK];
    if (lane == 0) {
        float bb = bias[0];
        float c0 = s0 + bb, c1 = s1 + bb;
        g_score[r0]     = c0;
        g_score[r0 + 1] = c1;
        ws[warp*2]   = c0;  wq[warp*2]   = c0*c0;
        ws[warp*2+1] = c1;  wq[warp*2+1] = c1*c1;
    }
    __syncthreads();
    if (threadIdx.x < 32) {
        // 32 values -> warp reduce
        float S = ws[threadIdx.x];
        float Q = wq[threadIdx.x];
#pragma unroll
        for (int off = 16; off > 0; off >>= 1) {
            S += __shfl_xor_sync(0xffffffffu, S, off);
            Q += __shfl_xor_sync(0xffffffffu, Q, off);
        }
        if (threadIdx.x == 0) { g_psum[blockIdx.x] = S; g_psq[blockIdx.x] = Q; }
    }
}

// ---------------------------------------------------------------------------
// K2: one CTA per batch.  Stable top-TOPN-smallest via 64-bit keys
// (bits(relu(normalized)) << 32) | index, 8-pass byte radix-select of the
// rank-(TOPN-1) key, collect, bitonic sort, emit indices.
// Bin pick is parallel (warp-0 scan) — no serial 256-bin walk.
// ---------------------------------------------------------------------------
__global__ __launch_bounds__(1024) void select_kernel(const float* __restrict__ gamma,
                                                      const float* __restrict__ beta) {
    extern __shared__ unsigned long long dyn[];
    unsigned long long* keys = dyn;          // SEQ
    unsigned long long* sel  = dyn + SEQ;    // TOPN

    __shared__ unsigned hist[256];
    __shared__ float red1[1024], red2[1024];
    __shared__ unsigned long long prefix_s;
    __shared__ int k_s;
    __shared__ unsigned cnt_s;

    const int tid = threadIdx.x;
    const int b   = blockIdx.x;

    // --- mean / var from K1 partials ---
    float S = 0.f, Q = 0.f;
    for (int i = tid; i < K1_BLOCKS; i += 1024) { S += g_psum[i]; Q += g_psq[i]; }
    red1[tid] = S; red2[tid] = Q;
    __syncthreads();
    for (int off = 512; off > 0; off >>= 1) {
        if (tid < off) { red1[tid] += red1[tid + off]; red2[tid] += red2[tid + off]; }
        __syncthreads();
    }
    float mean = red1[0] / (float)ROWS;
    float var  = red2[0] / (float)ROWS - mean * mean;
    if (var < 0.f) var = 0.f;
    float scale = rsqrtf(var + 1e-5f) * gamma[0];
    float shift = beta[0] - mean * scale;

    // --- build keys ---
    const float* sc = g_score + (size_t)b * SEQ;
    for (int i = tid; i < SEQ; i += 1024) {
        float r = fmaxf(0.f, fmaf(sc[i], scale, shift));
        keys[i] = ((unsigned long long)__float_as_uint(r) << 32) | (unsigned)i;
    }
    if (tid == 0) { prefix_s = 0ULL; k_s = TOPN - 1; cnt_s = 0u; }
    __syncthreads();

    // --- radix-select rank TOPN-1 (keys unique) ---
    unsigned long long prefix = 0ULL;
    for (int d = 7; d >= 0; --d) {
        for (int i = tid; i < 256; i += 1024) hist[i] = 0u;
        __syncthreads();
        const int sh = d * 8;
        const unsigned long long pmask = (d == 7) ? 0ULL : (~0ULL << (sh + 8));
        for (int i = tid; i < SEQ; i += 1024) {
            unsigned long long key = keys[i];
            if ((key & pmask) == prefix)
                atomicAdd(&hist[(unsigned)(key >> sh) & 255u], 1u);
        }
        int k = k_s;          // stable since last write was before a barrier
        __syncthreads();
        if (tid < 32) {
            // 8 bins per lane; exclusive scan across lanes
            unsigned v[8]; unsigned tot = 0u;
#pragma unroll
            for (int j = 0; j < 8; j++) { v[j] = hist[tid*8 + j]; tot += v[j]; }
            unsigned ex = tot;
#pragma unroll
            for (int off = 1; off < 32; off <<= 1) {
                unsigned n = __shfl_up_sync(0xffffffffu, ex, off);
                if (tid >= off) ex += n;
            }
            ex -= tot;   // exclusive prefix of this lane's 8-bin group
            if ((unsigned)k >= ex && (unsigned)k < ex + tot) {
                unsigned kk = (unsigned)k - ex;
                int bin = tid * 8;
#pragma unroll
                for (int j = 0; j < 8; j++) {
                    if (kk < v[j]) { bin = tid*8 + j; break; }
                    kk -= v[j];
                }
                prefix_s = prefix | ((unsigned long long)bin << sh);
                k_s = (int)kk;
            }
        }
        __syncthreads();
        prefix = prefix_s;
    }
    const unsigned long long cutoff = prefix;   // exactly TOPN keys <= cutoff

    // --- collect selected keys ---
    for (int i = tid; i < SEQ; i += 1024) {
        unsigned long long key = keys[i];
        if (key <= cutoff) {
            unsigned p = atomicAdd(&cnt_s, 1u);
            sel[p] = key;
        }
    }
    __syncthreads();

    // --- bitonic sort TOPN keys ascending ---
    for (int k = 2; k <= TOPN; k <<= 1) {
        for (int j = k >> 1; j > 0; j >>= 1) {
#pragma unroll
            for (int t = 0; t < TOPN / 1024; t++) {
                int i = tid + t * 1024;
                int l = i ^ j;
                if (l > i) {
                    unsigned long long a = sel[i], c = sel[l];
                    bool asc = ((i & k) == 0);
                    if ((a > c) == asc) { sel[i] = c; sel[l] = a; }
                }
            }
            __syncthreads();
        }
    }

    for (int r = tid; r < TOPN; r += 1024)
        g_idx[b * TOPN + r] = (unsigned)(sel[r] & 0xffffffffu);
}

// ---------------------------------------------------------------------------
// K3: gather rows: out[b, r, :] = x_select[b, idx[b,r], :]
// ---------------------------------------------------------------------------
__global__ __launch_bounds__(256) void gather_kernel(const float* __restrict__ xs,
                                                     float* __restrict__ out) {
    int rid  = blockIdx.x * 4 + (threadIdx.x >> 6);
    int lane = threadIdx.x & 63;
    int b    = rid >> 11;
    unsigned idx = g_idx[rid];
    const float4* src = (const float4*)(xs + ((size_t)b * SEQ + idx) * CH);
    float4* dst = (float4*)(out + (size_t)rid * CH);
    dst[lane] = src[lane];
}

// ---------------------------------------------------------------------------
extern "C" void kernel_launch(void* const* d_in, const int* in_sizes, int n_in,
                              void* d_out, int out_size) {
    const float* x_in  = (const float*)d_in[0];
    const float* x_sel = (const float*)d_in[1];
    const float* w     = (const float*)d_in[2];
    const float* bias  = (const float*)d_in[3];
    const float* gamma = (const float*)d_in[4];
    const float* beta  = (const float*)d_in[5];
    float* out = (float*)d_out;

    const int sel_smem = (SEQ + TOPN) * (int)sizeof(unsigned long long);  // 147456
    cudaFuncSetAttribute(select_kernel,
                         cudaFuncAttributeMaxDynamicSharedMemorySize, sel_smem);

    score_kernel<<<K1_BLOCKS, 512>>>(x_in, w, bias);
    select_kernel<<<BATCH, 1024, sel_smem>>>(gamma, beta);
    gather_kernel<<<(BATCH * TOPN) / 4, 256>>>(x_sel, out);
}